// round 10
// baseline (speedup 1.0000x reference)
#include <cuda_runtime.h>
#include <cuda_fp16.h>
#include <cstdint>
#include <math.h>

#define NODES 4096
#define EDGES 131072

// ---------------- device scratch ----------------
__device__ __align__(256) __half g_G1 [3ull * EDGES * 128]; // he@W4_l, fp16
__device__ __align__(256) float  g_h  [NODES * 128];
__device__ __align__(256) __half g_hSr[NODES * 128];
__device__ __align__(256) float  g_P1 [NODES * 128];
__device__ __align__(256) float  g_P23[NODES * 128];
__device__ __align__(256) __half g_S2h[NODES * 128];
__device__ __align__(256) float  g_vs [NODES];
__device__ __align__(256) __half g_Wt [20 * 16384];
__device__ __align__(256) __half g_Mt [3 * 8192];   // M_l = We@Gw4_l, Bt pad64
__device__ __align__(256) float  g_uvec[3 * 128];
__device__ __align__(256) float  g_svec[3 * 128];
__device__ __align__(256) float  g_cvec[3 * 128];

// ---------------- helpers ----------------
__device__ __forceinline__ uint32_t s2u(const void* p) {
    uint32_t a;
    asm("{ .reg .u64 t; cvta.to.shared.u64 t, %1; cvt.u32.u64 %0, t; }" : "=r"(a) : "l"(p));
    return a;
}
__device__ __forceinline__ uint32_t f2h2(float x, float y) {
    __half2 h = __floats2half2_rn(x, y);
    return *(uint32_t*)&h;
}
__device__ __forceinline__ void ldsm4(uint32_t d[4], uint32_t a) {
    asm volatile("ldmatrix.sync.aligned.m8n8.x4.shared.b16 {%0,%1,%2,%3}, [%4];"
                 : "=r"(d[0]), "=r"(d[1]), "=r"(d[2]), "=r"(d[3]) : "r"(a));
}
__device__ __forceinline__ void mma16(float d[4], const uint32_t a[4], uint32_t b0, uint32_t b1) {
    asm volatile("mma.sync.aligned.m16n8k16.row.col.f32.f16.f16.f32 "
                 "{%0,%1,%2,%3}, {%4,%5,%6,%7}, {%8,%9}, {%0,%1,%2,%3};"
                 : "+f"(d[0]), "+f"(d[1]), "+f"(d[2]), "+f"(d[3])
                 : "r"(a[0]), "r"(a[1]), "r"(a[2]), "r"(a[3]), "r"(b0), "r"(b1));
}
#define CP16(dst, src) asm volatile("cp.async.cg.shared.global [%0], [%1], 16;" :: "r"(dst), "l"(src))
#define CP_COMMIT()    asm volatile("cp.async.commit_group;")
#define CP_WAIT0()     asm volatile("cp.async.wait_group 0;" ::: "memory")

template <int ROWH>
__device__ __forceinline__ int swzh(int r, int c) { return r * ROWH + (c ^ ((r & 7) << 3)); }

template <int ROWS, int ROWH>
__device__ __forceinline__ void cpa_h(uint32_t sDst, const __half* __restrict__ g, int tid) {
    const int NCH = ROWS * ROWH / 8;
    #pragma unroll 4
    for (int i = tid; i < NCH; i += 256) {
        int r = i / (ROWH / 8), c = (i % (ROWH / 8)) * 8;
        CP16(sDst + swzh<ROWH>(r, c) * 2, g + (size_t)r * ROWH + c);
    }
}

// ------------- 128-row CTA GEMM: 8 warps 4m x 2n (warp tile 32x64) ----------
__device__ __forceinline__ void zacc8(float acc[2][8][4]) {
    #pragma unroll
    for (int i = 0; i < 2; ++i)
        #pragma unroll
        for (int j = 0; j < 8; ++j)
            #pragma unroll
            for (int k = 0; k < 4; ++k) acc[i][j][k] = 0.f;
}
template <int KH, int ROWH>
__device__ __forceinline__ void cta_gemm_h(uint32_t sAu, uint32_t sBu, int lane,
                                           int mbase, int nbase, float acc[2][8][4]) {
    int arow = lane & 15, acol = (lane >> 4) << 3;
    int bn = ((lane >> 4) & 1) * 8 + (lane & 7), bk = ((lane >> 3) & 1) * 8;
    #pragma unroll
    for (int k0 = 0; k0 < KH; ++k0) {
        int kh = k0 * 16;
        uint32_t a0[4], a1[4];
        ldsm4(a0, sAu + swzh<ROWH>(mbase + arow,      kh + acol) * 2);
        ldsm4(a1, sAu + swzh<ROWH>(mbase + 16 + arow, kh + acol) * 2);
        #pragma unroll
        for (int q8 = 0; q8 < 4; ++q8) {
            uint32_t b[4];
            ldsm4(b, sBu + swzh<ROWH>(nbase + q8 * 16 + bn, kh + bk) * 2);
            mma16(acc[0][q8 * 2],     a0, b[0], b[1]);
            mma16(acc[0][q8 * 2 + 1], a0, b[2], b[3]);
            mma16(acc[1][q8 * 2],     a1, b[0], b[1]);
            mma16(acc[1][q8 * 2 + 1], a1, b[2], b[3]);
        }
    }
}
// ------------- 64-row CTA GEMM (node kernels): 8 warps 2m x 4n --------------
__device__ __forceinline__ void zacc4(float acc[2][4][4]) {
    #pragma unroll
    for (int i = 0; i < 2; ++i)
        #pragma unroll
        for (int j = 0; j < 4; ++j)
            #pragma unroll
            for (int k = 0; k < 4; ++k) acc[i][j][k] = 0.f;
}
template <int KH, int ROWH>
__device__ __forceinline__ void cta_gemm64(uint32_t sAu, uint32_t sBu, int lane,
                                           int mbase, int nbase, float acc[2][4][4]) {
    int arow = lane & 15, acol = (lane >> 4) << 3;
    int bn = ((lane >> 4) & 1) * 8 + (lane & 7), bk = ((lane >> 3) & 1) * 8;
    #pragma unroll
    for (int k0 = 0; k0 < KH; ++k0) {
        int kh = k0 * 16;
        uint32_t a0[4], a1[4];
        ldsm4(a0, sAu + swzh<ROWH>(mbase + arow,      kh + acol) * 2);
        ldsm4(a1, sAu + swzh<ROWH>(mbase + 16 + arow, kh + acol) * 2);
        #pragma unroll
        for (int q8 = 0; q8 < 2; ++q8) {
            uint32_t b[4];
            ldsm4(b, sBu + swzh<ROWH>(nbase + q8 * 16 + bn, kh + bk) * 2);
            mma16(acc[0][q8 * 2],     a0, b[0], b[1]);
            mma16(acc[0][q8 * 2 + 1], a0, b[2], b[3]);
            mma16(acc[1][q8 * 2],     a1, b[0], b[1]);
            mma16(acc[1][q8 * 2 + 1], a1, b[2], b[3]);
        }
    }
}

// ---------------- pack_all: weights + hS + vs + M/u/s/c ----------------
__global__ void pack_all(const float* __restrict__ Wv, const float* __restrict__ We,
                         const float* __restrict__ Lw1, const float* __restrict__ Lw2,
                         const float* __restrict__ Lw3, const float* __restrict__ hS,
                         const int* __restrict__ Eidx, const float* __restrict__ mask,
                         const float* __restrict__ We_g, const float* __restrict__ We_b,
                         const float* __restrict__ We_b2) {
    int m = blockIdx.x, tid = threadIdx.x;
    if (m < 20) {
        const float* src; int Kin, ROWH;
        if (m == 0)      { src = Wv; Kin = 64; ROWH = 64; }
        else if (m == 1) { src = We; Kin = 48; ROWH = 64; }
        else {
            int l = (m - 2) / 6, q = (m - 2) % 6;
            if (q < 4)       src = Lw1 + ((size_t)l * 512 + q * 128) * 128;
            else if (q == 4) src = Lw2 + (size_t)l * 16384;
            else             src = Lw3 + (size_t)l * 16384;
            Kin = 128; ROWH = 128;
        }
        __half* dst = g_Wt + (size_t)m * 16384;
        int tot = 128 * ROWH;
        for (int i = tid; i < tot; i += 256) {
            int n = i / ROWH, k = i % ROWH;
            dst[i] = (k < Kin) ? __float2half_rn(src[(size_t)k * 128 + n]) : __half(0.f);
        }
    } else if (m < 52) {
        int b = m - 20;
        const float* src = hS + (size_t)b * 16384;
        __half* dst = g_hSr + (size_t)b * 16384;
        for (int i = tid; i < 16384; i += 256) dst[i] = __float2half_rn(src[i]);
    } else if (m < 68) {
        int nd = (m - 52) * 256 + tid;
        if (nd < NODES) {
            int b = nd >> 11;
            float s = 0.f;
            #pragma unroll 8
            for (int k = 0; k < 32; ++k) s += mask[(b << 11) + Eidx[nd * 32 + k]];
            g_vs[nd] = s;
        }
    } else if (m < 92) {
        // M_l[k][j] = sum_c We[k][c]*We_g[c]*W4_l[c][j]; stored Bt pad64
        int l = (m - 68) >> 3, part = (m - 68) & 7;
        const float* W4 = Lw1 + (size_t)l * 512 * 128 + 384 * 128;
        for (int e = part * 1024 + tid; e < part * 1024 + 1024; e += 256) {
            int j = e >> 6, k = e & 63;
            float v = 0.f;
            if (k < 48) {
                for (int c = 0; c < 128; ++c)
                    v += We[k * 128 + c] * We_g[c] * W4[c * 128 + j];
            }
            g_Mt[l * 8192 + j * 64 + k] = __float2half_rn(v);
        }
    } else {
        int l = m - 92;
        if (tid < 128) {
            const float* W4 = Lw1 + (size_t)l * 512 * 128 + 384 * 128;
            int j = tid;
            float u = 0.f, s = 0.f, cc = 0.f;
            for (int c = 0; c < 128; ++c) {
                float w4 = W4[c * 128 + j], gg = We_g[c];
                u += We_b[c] * gg * w4;
                s += gg * w4;
                cc += We_b2[c] * w4;
            }
            g_uvec[l * 128 + j] = u;
            g_svec[l * 128 + j] = s;
            g_cvec[l * 128 + j] = cc;
        }
    }
}

// ---------------- embed_g1: G1_l = he@W4_l via E@M_l, fused LN stats --------
// halfs: sAh 8192 | sWe 8192 | sM[3] 8192 each = 40960 halfs (80 KB)
// floats: sBe 128 | sU 384 | sS 384 | sC 384 | sRS 256 | sRQ 256 = 1792
#define SM_G1 (40960 * 2 + 1792 * 4)
__global__ void __launch_bounds__(256, 2)
embed_g1_k(const float* __restrict__ E, const float* __restrict__ We_b) {
    extern __shared__ __half smh[];
    __half* sAh = smh; __half* sWe = smh + 8192;
    float* fx = (float*)(smh + 40960);
    float* sBe = fx; float* sU = fx + 128; float* sS = fx + 512; float* sC = fx + 896;
    float* sRS = fx + 1280; float* sRQ = fx + 1536;
    uint32_t sAu = s2u(sAh), sWu = s2u(sWe);
    int tid = threadIdx.x, lane = tid & 31, wid = tid >> 5;
    int g = lane >> 2, t = lane & 3;
    int mbase = (wid & 3) * 32, nbase = (wid >> 2) * 64;

    cpa_h<128, 64>(sWu, g_Wt + 16384, tid);                 // We pad64
    #pragma unroll
    for (int l = 0; l < 3; ++l)
        cpa_h<128, 64>(s2u(smh + 16384 + l * 8192), g_Mt + l * 8192, tid);
    CP_COMMIT();
    if (tid < 128) {
        sBe[tid] = We_b[tid];
        #pragma unroll
        for (int l = 0; l < 3; ++l) {
            sU[l * 128 + tid] = g_uvec[l * 128 + tid];
            sS[l * 128 + tid] = g_svec[l * 128 + tid];
            sC[l * 128 + tid] = g_cvec[l * 128 + tid];
        }
    }
    // zero-pad cols 48..63 of sAh once (never rewritten)
    for (int i = tid; i < 512; i += 256) {
        int r = i >> 2, c = 48 + (i & 3) * 4;
        *(uint2*)((char*)sAh + swzh<64>(r, c) * 2) = make_uint2(0, 0);
    }
    CP_WAIT0(); __syncthreads();

    for (int tile = blockIdx.x; tile < 1024; tile += gridDim.x) {
        // load E tile (128 x 48 f32) -> fp16 swizzled
        for (int i = tid; i < 1536; i += 256) {
            int r = i / 12, c = (i % 12) * 4;
            float4 v = *(const float4*)(E + (size_t)tile * 6144 + r * 48 + c);
            uint2 w;
            w.x = f2h2(v.x, v.y); w.y = f2h2(v.z, v.w);
            *(uint2*)((char*)sAh + swzh<64>(r, c) * 2) = w;
        }
        __syncthreads();

        // stats GEMM: x = E@We + be ; per-row mu, inv
        float acc[2][8][4];
        zacc8(acc);
        cta_gemm_h<4, 64>(sAu, sWu, lane, mbase, nbase, acc);

        float p[4] = {0, 0, 0, 0}, q[4] = {0, 0, 0, 0};
        #pragma unroll
        for (int mt = 0; mt < 2; ++mt)
            #pragma unroll
            for (int nt = 0; nt < 8; ++nt) {
                int c0 = nbase + nt * 8 + t * 2;
                float* d = acc[mt][nt];
                d[0] += sBe[c0]; d[1] += sBe[c0 + 1];
                d[2] += sBe[c0]; d[3] += sBe[c0 + 1];
                p[mt*2]   += d[0] + d[1];  q[mt*2]   += d[0]*d[0] + d[1]*d[1];
                p[mt*2+1] += d[2] + d[3];  q[mt*2+1] += d[2]*d[2] + d[3]*d[3];
            }
        #pragma unroll
        for (int i = 0; i < 4; ++i) {
            p[i] += __shfl_xor_sync(0xffffffffu, p[i], 1);
            p[i] += __shfl_xor_sync(0xffffffffu, p[i], 2);
            q[i] += __shfl_xor_sync(0xffffffffu, q[i], 1);
            q[i] += __shfl_xor_sync(0xffffffffu, q[i], 2);
        }
        int half_ = nbase >> 6;
        if (t == 0) {
            #pragma unroll
            for (int i = 0; i < 4; ++i) {
                int r = mbase + (i >> 1) * 16 + (i & 1) * 8 + g;
                sRS[r * 2 + half_] = p[i];
                sRQ[r * 2 + half_] = q[i];
            }
        }
        __syncthreads();

        float muv[4], invv[4];
        #pragma unroll
        for (int i = 0; i < 4; ++i) {
            int r = mbase + (i >> 1) * 16 + (i & 1) * 8 + g;
            float mu = (sRS[r * 2] + sRS[r * 2 + 1]) * (1.f / 128.f);
            float qq = sRQ[r * 2] + sRQ[r * 2 + 1];
            float var = (qq - 128.f * mu * mu) * (1.f / 127.f);
            muv[i] = mu;
            invv[i] = 1.f / (sqrtf(fmaxf(var, 0.f)) + 1e-6f);
        }

        // three G1 GEMMs: G1_l = inv*(E@M_l + u - mu*s) + c
        #pragma unroll 1
        for (int l = 0; l < 3; ++l) {
            zacc8(acc);
            cta_gemm_h<4, 64>(sAu, s2u(smh + 16384 + l * 8192), lane, mbase, nbase, acc);
            __half* outp = g_G1 + ((size_t)l * 1024 + tile) * 16384;
            #pragma unroll
            for (int mt = 0; mt < 2; ++mt)
                #pragma unroll
                for (int jj = 0; jj < 2; ++jj) {
                    int i = mt * 2 + jj;
                    int r = mbase + mt * 16 + jj * 8 + g;
                    float mu = muv[i], inv = invv[i];
                    #pragma unroll
                    for (int nt = 0; nt < 8; ++nt) {
                        int c0 = nbase + nt * 8 + t * 2;
                        float* d = acc[mt][nt];
                        float v0 = (d[jj*2]   + sU[l*128+c0]   - mu * sS[l*128+c0])   * inv + sC[l*128+c0];
                        float v1 = (d[jj*2+1] + sU[l*128+c0+1] - mu * sS[l*128+c0+1]) * inv + sC[l*128+c0+1];
                        *(uint32_t*)(outp + (size_t)r * 128 + c0) = f2h2(v0, v1);
                    }
                }
        }
        __syncthreads();
    }
}

// ---------------- light edge layer: epi1 + GEMM2 + reduce -------------------
// halfs: sAh 16384 | sLw2 16384 ; floats: sP1 512 | sVm 128 | sBb2 128 | sGidx 128
#define SM_E2 (32768 * 2 + 896 * 4)
__global__ void __launch_bounds__(256, 2)
edge2_k(const int* __restrict__ Eidx, const float* __restrict__ mask,
        const float* __restrict__ Lb2, int layer) {
    extern __shared__ __half smh[];
    __half* sAh = smh; __half* sLw2 = smh + 16384;
    float* fx = (float*)(smh + 32768);
    float* sP1 = fx; float* sVm = fx + 512; float* sBb2 = fx + 640;
    int* sGidx = (int*)(fx + 768);
    uint32_t sAu = s2u(sAh), sWu = s2u(sLw2);
    int tid = threadIdx.x, lane = tid & 31, wid = tid >> 5;
    int mbase = (wid & 3) * 32, nbase = (wid >> 2) * 64;
    int g = lane >> 2, t = lane & 3;

    cpa_h<128, 128>(sWu, g_Wt + (size_t)(2 + layer * 6 + 4) * 16384, tid);  // Lw2
    cpa_h<128, 128>(sAu, g_G1 + ((size_t)layer * 1024 + blockIdx.x) * 16384, tid);
    CP_COMMIT();
    if (tid < 128) sBb2[tid] = Lb2[layer * 128 + tid];

    for (int tile = blockIdx.x; tile < 1024; tile += gridDim.x) {
        __syncthreads();
        int base4 = tile * 4;
        if (tid < 128) {
            int nd = base4 + (tid >> 5);
            int idx = Eidx[nd * 32 + (tid & 31)];
            int gi = ((nd >> 11) << 11) + idx;
            sGidx[tid] = gi;
            sVm[tid] = mask[gi];
        }
        for (int i = tid; i < 512; i += 256)
            sP1[i] = g_P1[(size_t)base4 * 128 + i];
        CP_WAIT0(); __syncthreads();

        // epilogue1 in-place: m1 = relu(G1 + P1 + P23gather) -> sAh fp16
        #pragma unroll 2
        for (int i = tid; i < 2048; i += 256) {
            int r = i >> 4, c = (i & 15) * 8;
            char* ap = (char*)sAh + swzh<128>(r, c) * 2;
            uint4 uu = *(uint4*)ap;
            float2 a0 = __half22float2(*(__half2*)&uu.x);
            float2 a1 = __half22float2(*(__half2*)&uu.y);
            float2 a2 = __half22float2(*(__half2*)&uu.z);
            float2 a3 = __half22float2(*(__half2*)&uu.w);
            const float* qp = g_P23 + (size_t)sGidx[r] * 128 + c;
            float4 q0 = *(const float4*)qp;
            float4 q1 = *(const float4*)(qp + 4);
            const float* pp = sP1 + ((r >> 5) << 7) + c;
            float4 p0 = *(const float4*)pp;
            float4 p1v = *(const float4*)(pp + 4);
            uu.x = f2h2(fmaxf(a0.x + q0.x + p0.x, 0.f),  fmaxf(a0.y + q0.y + p0.y, 0.f));
            uu.y = f2h2(fmaxf(a1.x + q0.z + p0.z, 0.f),  fmaxf(a1.y + q0.w + p0.w, 0.f));
            uu.z = f2h2(fmaxf(a2.x + q1.x + p1v.x, 0.f), fmaxf(a2.y + q1.y + p1v.y, 0.f));
            uu.w = f2h2(fmaxf(a3.x + q1.z + p1v.z, 0.f), fmaxf(a3.y + q1.w + p1v.w, 0.f));
            *(uint4*)ap = uu;
        }
        __syncthreads();

        float acc[2][8][4];
        zacc8(acc);
        cta_gemm_h<8, 128>(sAu, sWu, lane, mbase, nbase, acc);
        __syncthreads();

        int nxt = tile + gridDim.x;
        if (nxt < 1024) {
            cpa_h<128, 128>(sAu, g_G1 + ((size_t)layer * 1024 + nxt) * 16384, tid);
            CP_COMMIT();
        }

        // epilogue2: weighted segment sum of relu(D + b2)
        float part[8][2];
        #pragma unroll
        for (int nt = 0; nt < 8; ++nt) { part[nt][0] = 0.f; part[nt][1] = 0.f; }
        #pragma unroll
        for (int mt = 0; mt < 2; ++mt) {
            int r0 = mbase + mt * 16 + g, r1 = r0 + 8;
            float v0 = sVm[r0], v1 = sVm[r1];
            #pragma unroll
            for (int nt = 0; nt < 8; ++nt) {
                int c0 = nbase + nt * 8 + t * 2;
                float* d = acc[mt][nt];
                part[nt][0] += fmaxf(d[0] + sBb2[c0],   0.f) * v0
                             + fmaxf(d[2] + sBb2[c0],   0.f) * v1;
                part[nt][1] += fmaxf(d[1] + sBb2[c0+1], 0.f) * v0
                             + fmaxf(d[3] + sBb2[c0+1], 0.f) * v1;
            }
        }
        #pragma unroll
        for (int nt = 0; nt < 8; ++nt)
            #pragma unroll
            for (int j = 0; j < 2; ++j) {
                float v = part[nt][j];
                v += __shfl_xor_sync(0xffffffffu, v, 4);
                v += __shfl_xor_sync(0xffffffffu, v, 8);
                v += __shfl_xor_sync(0xffffffffu, v, 16);
                part[nt][j] = v;
            }
        if (g == 0) {
            int node = base4 + (wid & 3);
            #pragma unroll
            for (int nt = 0; nt < 8; ++nt) {
                int c0 = nbase + nt * 8 + t * 2;
                *(uint32_t*)(g_S2h + (size_t)node * 128 + c0) = f2h2(part[nt][0], part[nt][1]);
            }
        }
    }
}

// ---------------- proj phase (M=64) ----------------
__device__ __forceinline__ void proj_phase64(uint32_t sA2u, uint32_t sA1u,
                                             uint32_t sW0u, uint32_t sW1u, uint32_t sW2u,
                                             const float* sBias1, int blk,
                                             int lane, int wid) {
    int mbase = (wid & 1) * 32, nbase = (wid >> 1) * 32;
    int g = lane >> 2, t = lane & 3;
    float acc[2][4][4];

    zacc4(acc);
    cta_gemm64<8, 128>(sA2u, sW0u, lane, mbase, nbase, acc);
    #pragma unroll
    for (int mt = 0; mt < 2; ++mt) {
        int r0 = mbase + mt * 16 + g;
        #pragma unroll
        for (int nt = 0; nt < 4; ++nt) {
            int c0 = nbase + nt * 8 + t * 2;
            float* d = acc[mt][nt];
            *(float2*)(g_P1 + ((size_t)blk * 64 + r0) * 128 + c0) =
                make_float2(d[0] + sBias1[c0], d[1] + sBias1[c0 + 1]);
            *(float2*)(g_P1 + ((size_t)blk * 64 + r0 + 8) * 128 + c0) =
                make_float2(d[2] + sBias1[c0], d[3] + sBias1[c0 + 1]);
        }
    }
    zacc4(acc);
    cta_gemm64<8, 128>(sA2u, sW1u, lane, mbase, nbase, acc);
    CP_WAIT0(); __syncthreads();
    cta_gemm64<8, 128>(sA1u, sW2u, lane, mbase, nbase, acc);
    #pragma unroll
    for (int mt = 0; mt < 2; ++mt) {
        int r0 = mbase + mt * 16 + g;
        #pragma unroll
        for (int nt = 0; nt < 4; ++nt) {
            int c0 = nbase + nt * 8 + t * 2;
            float* d = acc[mt][nt];
            *(float2*)(g_P23 + ((size_t)blk * 64 + r0) * 128 + c0) = make_float2(d[0], d[1]);
            *(float2*)(g_P23 + ((size_t)blk * 64 + r0 + 8) * 128 + c0) = make_float2(d[2], d[3]);
        }
    }
}

#define SM_NP ((8192 * 2 + 3 * 16384) * 2 + 1152 * 4)

// ---------------- embed_node + proj(layer 0), M=64, grid 64 -----------------
__global__ void __launch_bounds__(256)
embed_node_proj_k(const float* __restrict__ V, const float* __restrict__ bb,
                  const float* __restrict__ gg, const float* __restrict__ b2,
                  const float* __restrict__ Lb1) {
    extern __shared__ __half smh[];
    __half* sA1 = smh;            __half* sA2 = smh + 8192;
    __half* sW0 = smh + 16384;    __half* sW1 = smh + 32768;  __half* sW2 = smh + 49152;
    float* fx = (float*)(smh + 65536);
    float* sBias = fx; float* sG = fx + 128; float* sB2 = fx + 256;
    float* sBias1 = fx + 384;
    float* sRS = fx + 512; float* sRQ = fx + 768;
    uint32_t sA1u = s2u(sA1), sA2u = s2u(sA2);
    uint32_t sW0u = s2u(sW0), sW1u = s2u(sW1), sW2u = s2u(sW2);
    int tid = threadIdx.x, lane = tid & 31, wid = tid >> 5, blk = blockIdx.x;
    int g = lane >> 2, t = lane & 3;
    int mbase = (wid & 1) * 32, nbase = (wid >> 1) * 32;
    int ng = wid >> 1;

    cpa_h<128, 64>(sW2u, g_Wt, tid);
    cpa_h<128, 128>(sW0u, g_Wt + (size_t)2 * 16384, tid);
    cpa_h<128, 128>(sW1u, g_Wt + (size_t)3 * 16384, tid);
    CP_COMMIT();
    for (int i = tid; i < 512; i += 256) {
        int r = i >> 3, gc = (i & 7) * 8;
        const float* xp = V + ((size_t)blk * 64 + r) * 64 + gc;
        float4 v0 = *(const float4*)xp;
        float4 v1 = *(const float4*)(xp + 4);
        uint4 u;
        u.x = f2h2(v0.x, v0.y); u.y = f2h2(v0.z, v0.w);
        u.z = f2h2(v1.x, v1.y); u.w = f2h2(v1.z, v1.w);
        *(uint4*)((char*)sA1 + swzh<64>(r, gc) * 2) = u;
    }
    if (tid < 128) {
        sBias[tid] = bb[tid]; sG[tid] = gg[tid]; sB2[tid] = b2[tid];
        sBias1[tid] = Lb1[tid];
    }
    CP_WAIT0(); __syncthreads();

    float acc[2][4][4];
    zacc4(acc);
    cta_gemm64<4, 64>(sA1u, sW2u, lane, mbase, nbase, acc);
    __syncthreads();
    cpa_h<64, 128>(sA1u, g_hSr + (size_t)blk * 8192, tid);
    cpa_h<128, 128>(sW2u, g_Wt + (size_t)4 * 16384, tid);
    CP_COMMIT();

    float p[4] = {0,0,0,0}, q[4] = {0,0,0,0};
    #pragma unroll
    for (int mt = 0; mt < 2; ++mt)
        #pragma unroll
        for (int nt = 0; nt < 4; ++nt) {
            int c0 = nbase + nt * 8 + t * 2;
            float* d = acc[mt][nt];
            d[0] += sBias[c0]; d[1] += sBias[c0 + 1];
            d[2] += sBias[c0]; d[3] += sBias[c0 + 1];
            p[mt*2]   += d[0] + d[1];  q[mt*2]   += d[0]*d[0] + d[1]*d[1];
            p[mt*2+1] += d[2] + d[3];  q[mt*2+1] += d[2]*d[2] + d[3]*d[3];
        }
    #pragma unroll
    for (int i = 0; i < 4; ++i) {
        p[i] += __shfl_xor_sync(0xffffffffu, p[i], 1);
        p[i] += __shfl_xor_sync(0xffffffffu, p[i], 2);
        q[i] += __shfl_xor_sync(0xffffffffu, q[i], 1);
        q[i] += __shfl_xor_sync(0xffffffffu, q[i], 2);
    }
    if (t == 0) {
        #pragma unroll
        for (int i = 0; i < 4; ++i) {
            int r = mbase + (i >> 1) * 16 + (i & 1) * 8 + g;
            sRS[r * 4 + ng] = p[i];
            sRQ[r * 4 + ng] = q[i];
        }
    }
    __syncthreads();
    #pragma unroll
    for (int mt = 0; mt < 2; ++mt)
        #pragma unroll
        for (int jj = 0; jj < 2; ++jj) {
            int r = mbase + mt * 16 + jj * 8 + g;
            float mu = (sRS[r*4] + sRS[r*4+1] + sRS[r*4+2] + sRS[r*4+3]) * (1.f / 128.f);
            float qq = sRQ[r*4] + sRQ[r*4+1] + sRQ[r*4+2] + sRQ[r*4+3];
            float var = (qq - 128.f * mu * mu) * (1.f / 127.f);
            float inv = 1.f / (sqrtf(fmaxf(var, 0.f)) + 1e-6f);
            #pragma unroll
            for (int nt = 0; nt < 4; ++nt) {
                int c0 = nbase + nt * 8 + t * 2;
                float* d = acc[mt][nt];
                float v0 = sG[c0]     * (d[jj*2]   - mu) * inv + sB2[c0];
                float v1 = sG[c0 + 1] * (d[jj*2+1] - mu) * inv + sB2[c0 + 1];
                *(float2*)(g_h + ((size_t)blk * 64 + r) * 128 + c0) = make_float2(v0, v1);
                *(uint32_t*)((char*)sA2 + swzh<128>(r, c0) * 2) = f2h2(v0, v1);
            }
        }
    __syncthreads();
    proj_phase64(sA2u, sA1u, sW0u, sW1u, sW2u, sBias1, blk, lane, wid);
}

// ---------------- node_fused: fin(layer) + proj(layer+1), M=64 --------------
__global__ void __launch_bounds__(256)
node_fused_k(const float* __restrict__ mask, const float* __restrict__ Lb3,
             const float* __restrict__ Lng, const float* __restrict__ Lnb,
             const float* __restrict__ Lb1, int layer, int last,
             float* __restrict__ outp) {
    extern __shared__ __half smh[];
    __half* sA1 = smh;            __half* sA2 = smh + 8192;
    __half* sW0 = smh + 16384;    __half* sW1 = smh + 32768;  __half* sW2 = smh + 49152;
    float* fx = (float*)(smh + 65536);
    float* sB3 = fx; float* sLg = fx + 128; float* sLb = fx + 256;
    float* sBias1 = fx + 384;
    float* sRS = fx + 512; float* sRQ = fx + 768;
    float* sVs = fx + 1024; float* sMk = fx + 1088;
    uint32_t sA1u = s2u(sA1), sA2u = s2u(sA2);
    uint32_t sW0u = s2u(sW0), sW1u = s2u(sW1), sW2u = s2u(sW2);
    int tid = threadIdx.x, lane = tid & 31, wid = tid >> 5, blk = blockIdx.x;
    int wbase = 2 + layer * 6, wnext = 2 + (layer + 1) * 6;
    int g = lane >> 2, t = lane & 3;
    int mbase = (wid & 1) * 32, nbase = (wid >> 1) * 32;
    int ng = wid >> 1;

    cpa_h<64, 128>(sA1u, g_S2h + (size_t)blk * 8192, tid);
    cpa_h<128, 128>(sW2u, g_Wt + (size_t)(wbase + 5) * 16384, tid);
    if (!last) {
        cpa_h<128, 128>(sW0u, g_Wt + (size_t)(wnext + 0) * 16384, tid);
        cpa_h<128, 128>(sW1u, g_Wt + (size_t)(wnext + 1) * 16384, tid);
    }
    CP_COMMIT();
    if (tid < 128) {
        sB3[tid] = Lb3[layer * 128 + tid];
        sLg[tid] = Lng[layer * 128 + tid];
        sLb[tid] = Lnb[layer * 128 + tid];
        if (!last) sBias1[tid] = Lb1[(layer + 1) * 128 + tid];
    }
    if (tid < 64) {
        sVs[tid] = g_vs[blk * 64 + tid];
        sMk[tid] = mask[blk * 64 + tid];
    }
    CP_WAIT0(); __syncthreads();

    float acc[2][4][4];
    zacc4(acc);
    cta_gemm64<8, 128>(sA1u, sW2u, lane, mbase, nbase, acc);
    __syncthreads();
    if (!last) {
        cpa_h<64, 128>(sA1u, g_hSr + (size_t)blk * 8192, tid);
        cpa_h<128, 128>(sW2u, g_Wt + (size_t)(wnext + 2) * 16384, tid);
        CP_COMMIT();
    }

    const float i30 = 1.f / 30.f;
    float p[4] = {0,0,0,0}, q[4] = {0,0,0,0};
    #pragma unroll
    for (int mt = 0; mt < 2; ++mt) {
        int r0 = mbase + mt * 16 + g, r1 = r0 + 8;
        float vs0 = sVs[r0] * i30, vs1 = sVs[r1] * i30;
        #pragma unroll
        for (int nt = 0; nt < 4; ++nt) {
            int c0 = nbase + nt * 8 + t * 2;
            float* d = acc[mt][nt];
            float2 h0 = *(const float2*)(g_h + ((size_t)(blk * 64 + r0)) * 128 + c0);
            float2 h1 = *(const float2*)(g_h + ((size_t)(blk * 64 + r1)) * 128 + c0);
            d[0] = d[0] * i30 + vs0 * sB3[c0]     + h0.x;
            d[1] = d[1] * i30 + vs0 * sB3[c0 + 1] + h0.y;
            d[2] = d[2] * i30 + vs1 * sB3[c0]     + h1.x;
            d[3] = d[3] * i30 + vs1 * sB3[c0 + 1] + h1.y;
            p[mt*2]   += d[0] + d[1];  q[mt*2]   += d[0]*d[0] + d[1]*d[1];
            p[mt*2+1] += d[2] + d[3];  q[mt*2+1] += d[2]*d[2] + d[3]*d[3];
        }
    }
    #pragma unroll
    for (int i = 0; i < 4; ++i) {
        p[i] += __shfl_xor_sync(0xffffffffu, p[i], 1);
        p[i] += __shfl_xor_sync(0xffffffffu, p[i], 2);
        q[i] += __shfl_xor_sync(0xffffffffu, q[i], 1);
        q[i] += __shfl_xor_sync(0xffffffffu, q[i], 2);
    }
    if (t == 0) {
        #pragma unroll
        for (int i = 0; i < 4; ++i) {
            int r = mbase + (i >> 1) * 16 + (i & 1) * 8 + g;
            sRS[r * 4 + ng] = p[i];
            sRQ[r * 4 + ng] = q[i];
        }
    }
    __syncthreads();
    #pragma unroll
    for (int mt = 0; mt < 2; ++mt)
        #pragma unroll
        for (int jj = 0; jj < 2; ++jj) {
            int r = mbase + mt * 16 + jj * 8 + g;
            float mu = (sRS[r*4] + sRS[r*4+1] + sRS[r*4+2] + sRS[r*4+3]) * (1.f / 128.f);
            float qq = sRQ[r*4] + sRQ[r*4+1] + sRQ[r*4+2] + sRQ[r*4+3];
            float var = (qq - 128.f * mu * mu) * (1.f / 127.f);
            float inv = 1.f / (sqrtf(fmaxf(var, 0.f)) + 1e-6f);
            float mk = sMk[r];
            #pragma unroll
            for (int nt = 0; nt < 4; ++nt) {
                int c0 = nbase + nt * 8 + t * 2;
                float* d = acc[mt][nt];
                float v0 = (sLg[c0]     * (d[jj*2]   - mu) * inv + sLb[c0])     * mk;
                float v1 = (sLg[c0 + 1] * (d[jj*2+1] - mu) * inv + sLb[c0 + 1]) * mk;
                size_t off = ((size_t)blk * 64 + r) * 128 + c0;
                if (last) {
                    *(float2*)(outp + off) = make_float2(v0, v1);
                } else {
                    *(float2*)(g_h + off) = make_float2(v0, v1);
                    *(uint32_t*)((char*)sA2 + swzh<128>(r, c0) * 2) = f2h2(v0, v1);
                }
            }
        }
    if (last) return;
    __syncthreads();
    proj_phase64(sA2u, sA1u, sW0u, sW1u, sW2u, sBias1, blk, lane, wid);
}

// ---------------- launch ----------------
extern "C" void kernel_launch(void* const* d_in, const int* in_sizes, int n_in,
                              void* d_out, int out_size) {
    const float* V     = (const float*)d_in[0];
    const float* E     = (const float*)d_in[1];
    const float* hS    = (const float*)d_in[2];
    const int*   E_idx = (const int*)  d_in[3];
    const float* mask  = (const float*)d_in[4];
    const float* Wv_w  = (const float*)d_in[5];
    const float* Wv_b  = (const float*)d_in[6];
    const float* Wv_g  = (const float*)d_in[7];
    const float* Wv_b2 = (const float*)d_in[8];
    const float* We_w  = (const float*)d_in[9];
    const float* We_b  = (const float*)d_in[10];
    const float* We_g  = (const float*)d_in[11];
    const float* We_b2 = (const float*)d_in[12];
    const float* Lw1   = (const float*)d_in[13];
    const float* Lb1   = (const float*)d_in[14];
    const float* Lw2   = (const float*)d_in[15];
    const float* Lb2   = (const float*)d_in[16];
    const float* Lw3   = (const float*)d_in[17];
    const float* Lb3   = (const float*)d_in[18];
    const float* Ln_g  = (const float*)d_in[19];
    const float* Ln_b  = (const float*)d_in[20];
    float* out = (float*)d_out;

    cudaFuncSetAttribute(embed_g1_k,        cudaFuncAttributeMaxDynamicSharedMemorySize, SM_G1);
    cudaFuncSetAttribute(edge2_k,           cudaFuncAttributeMaxDynamicSharedMemorySize, SM_E2);
    cudaFuncSetAttribute(embed_node_proj_k, cudaFuncAttributeMaxDynamicSharedMemorySize, SM_NP);
    cudaFuncSetAttribute(node_fused_k,      cudaFuncAttributeMaxDynamicSharedMemorySize, SM_NP);

    pack_all<<<95, 256>>>(Wv_w, We_w, Lw1, Lw2, Lw3, hS, E_idx, mask,
                          We_g, We_b, We_b2);
    embed_node_proj_k<<<64, 256, SM_NP>>>(V, Wv_b, Wv_g, Wv_b2, Lb1);
    embed_g1_k<<<304, 256, SM_G1>>>(E, We_b);

    for (int layer = 0; layer < 3; ++layer) {
        edge2_k<<<304, 256, SM_E2>>>(E_idx, mask, Lb2, layer);
        node_fused_k<<<64, 256, SM_NP>>>(mask, Lb3, Ln_g, Ln_b, Lb1,
                                         layer, layer == 2 ? 1 : 0, out);
    }
}

// round 11
// speedup vs baseline: 1.4805x; 1.4805x over previous
#include <cuda_runtime.h>
#include <cuda_fp16.h>
#include <cstdint>
#include <math.h>

#define NODES 4096
#define EDGES 131072

// ---------------- device scratch ----------------
__device__ __align__(256) __half g_her[EDGES * 128];
__device__ __align__(256) float  g_h  [NODES * 128];
__device__ __align__(256) __half g_hSr[NODES * 128];
__device__ __align__(256) float  g_P1 [NODES * 128];
__device__ __align__(256) __half g_P23[NODES * 128];   // fp16 now
__device__ __align__(256) __half g_S2h[NODES * 128];
__device__ __align__(256) float  g_vs [NODES];
__device__ __align__(256) __half g_Wt [20 * 16384];

// ---------------- helpers ----------------
__device__ __forceinline__ uint32_t s2u(const void* p) {
    uint32_t a;
    asm("{ .reg .u64 t; cvta.to.shared.u64 t, %1; cvt.u32.u64 %0, t; }" : "=r"(a) : "l"(p));
    return a;
}
__device__ __forceinline__ uint32_t f2h2(float x, float y) {
    __half2 h = __floats2half2_rn(x, y);
    return *(uint32_t*)&h;
}
__device__ __forceinline__ void ldsm4(uint32_t d[4], uint32_t a) {
    asm volatile("ldmatrix.sync.aligned.m8n8.x4.shared.b16 {%0,%1,%2,%3}, [%4];"
                 : "=r"(d[0]), "=r"(d[1]), "=r"(d[2]), "=r"(d[3]) : "r"(a));
}
__device__ __forceinline__ void mma16(float d[4], const uint32_t a[4], uint32_t b0, uint32_t b1) {
    asm volatile("mma.sync.aligned.m16n8k16.row.col.f32.f16.f16.f32 "
                 "{%0,%1,%2,%3}, {%4,%5,%6,%7}, {%8,%9}, {%0,%1,%2,%3};"
                 : "+f"(d[0]), "+f"(d[1]), "+f"(d[2]), "+f"(d[3])
                 : "r"(a[0]), "r"(a[1]), "r"(a[2]), "r"(a[3]), "r"(b0), "r"(b1));
}
#define CP16(dst, src) asm volatile("cp.async.cg.shared.global [%0], [%1], 16;" :: "r"(dst), "l"(src))
#define CP_COMMIT()    asm volatile("cp.async.commit_group;")
#define CP_WAIT0()     asm volatile("cp.async.wait_group 0;" ::: "memory")
#define CP_WAIT1()     asm volatile("cp.async.wait_group 1;" ::: "memory")

template <int ROWH>
__device__ __forceinline__ int swzh(int r, int c) { return r * ROWH + (c ^ ((r & 7) << 3)); }

template <int ROWS, int ROWH>
__device__ __forceinline__ void cpa_h(uint32_t sDst, const __half* __restrict__ g, int tid) {
    const int NCH = ROWS * ROWH / 8;
    #pragma unroll 4
    for (int i = tid; i < NCH; i += 256) {
        int r = i / (ROWH / 8), c = (i % (ROWH / 8)) * 8;
        CP16(sDst + swzh<ROWH>(r, c) * 2, g + (size_t)r * ROWH + c);
    }
}

// ------------- 128-row CTA GEMM (edge kernels): 8 warps 4m x 2n --------------
__device__ __forceinline__ void zacc8(float acc[2][8][4]) {
    #pragma unroll
    for (int i = 0; i < 2; ++i)
        #pragma unroll
        for (int j = 0; j < 8; ++j)
            #pragma unroll
            for (int k = 0; k < 4; ++k) acc[i][j][k] = 0.f;
}
template <int KH, int ROWH>
__device__ __forceinline__ void cta_gemm_h(uint32_t sAu, uint32_t sBu, int lane,
                                           int mbase, int nbase, float acc[2][8][4]) {
    int arow = lane & 15, acol = (lane >> 4) << 3;
    int bn = ((lane >> 4) & 1) * 8 + (lane & 7), bk = ((lane >> 3) & 1) * 8;
    #pragma unroll
    for (int k0 = 0; k0 < KH; ++k0) {
        int kh = k0 * 16;
        uint32_t a0[4], a1[4];
        ldsm4(a0, sAu + swzh<ROWH>(mbase + arow,      kh + acol) * 2);
        ldsm4(a1, sAu + swzh<ROWH>(mbase + 16 + arow, kh + acol) * 2);
        #pragma unroll
        for (int q8 = 0; q8 < 4; ++q8) {
            uint32_t b[4];
            ldsm4(b, sBu + swzh<ROWH>(nbase + q8 * 16 + bn, kh + bk) * 2);
            mma16(acc[0][q8 * 2],     a0, b[0], b[1]);
            mma16(acc[0][q8 * 2 + 1], a0, b[2], b[3]);
            mma16(acc[1][q8 * 2],     a1, b[0], b[1]);
            mma16(acc[1][q8 * 2 + 1], a1, b[2], b[3]);
        }
    }
}
// ------------- 64-row CTA GEMM (node kernels): 8 warps 2m x 4n ---------------
__device__ __forceinline__ void zacc4(float acc[2][4][4]) {
    #pragma unroll
    for (int i = 0; i < 2; ++i)
        #pragma unroll
        for (int j = 0; j < 4; ++j)
            #pragma unroll
            for (int k = 0; k < 4; ++k) acc[i][j][k] = 0.f;
}
template <int KH, int ROWH>
__device__ __forceinline__ void cta_gemm64(uint32_t sAu, uint32_t sBu, int lane,
                                           int mbase, int nbase, float acc[2][4][4]) {
    int arow = lane & 15, acol = (lane >> 4) << 3;
    int bn = ((lane >> 4) & 1) * 8 + (lane & 7), bk = ((lane >> 3) & 1) * 8;
    #pragma unroll
    for (int k0 = 0; k0 < KH; ++k0) {
        int kh = k0 * 16;
        uint32_t a0[4], a1[4];
        ldsm4(a0, sAu + swzh<ROWH>(mbase + arow,      kh + acol) * 2);
        ldsm4(a1, sAu + swzh<ROWH>(mbase + 16 + arow, kh + acol) * 2);
        #pragma unroll
        for (int q8 = 0; q8 < 2; ++q8) {
            uint32_t b[4];
            ldsm4(b, sBu + swzh<ROWH>(nbase + q8 * 16 + bn, kh + bk) * 2);
            mma16(acc[0][q8 * 2],     a0, b[0], b[1]);
            mma16(acc[0][q8 * 2 + 1], a0, b[2], b[3]);
            mma16(acc[1][q8 * 2],     a1, b[0], b[1]);
            mma16(acc[1][q8 * 2 + 1], a1, b[2], b[3]);
        }
    }
}

// ---------------- pack_all ----------------
__global__ void pack_all(const float* __restrict__ Wv, const float* __restrict__ We,
                         const float* __restrict__ Lw1, const float* __restrict__ Lw2,
                         const float* __restrict__ Lw3, const float* __restrict__ hS,
                         const int* __restrict__ Eidx, const float* __restrict__ mask) {
    int m = blockIdx.x, tid = threadIdx.x;
    if (m < 20) {
        const float* src; int Kin, ROWH;
        if (m == 0)      { src = Wv; Kin = 64; ROWH = 64; }
        else if (m == 1) { src = We; Kin = 48; ROWH = 64; }
        else {
            int l = (m - 2) / 6, q = (m - 2) % 6;
            if (q < 4)       src = Lw1 + ((size_t)l * 512 + q * 128) * 128;
            else if (q == 4) src = Lw2 + (size_t)l * 16384;
            else             src = Lw3 + (size_t)l * 16384;
            Kin = 128; ROWH = 128;
        }
        __half* dst = g_Wt + (size_t)m * 16384;
        int tot = 128 * ROWH;
        for (int i = tid; i < tot; i += 256) {
            int n = i / ROWH, k = i % ROWH;
            dst[i] = (k < Kin) ? __float2half_rn(src[(size_t)k * 128 + n]) : __half(0.f);
        }
    } else if (m < 52) {
        int b = m - 20;
        const float* src = hS + (size_t)b * 16384;
        __half* dst = g_hSr + (size_t)b * 16384;
        for (int i = tid; i < 16384; i += 256) dst[i] = __float2half_rn(src[i]);
    } else {
        int nd = (m - 52) * 256 + tid;
        if (nd < NODES) {
            int b = nd >> 11;
            float s = 0.f;
            #pragma unroll 8
            for (int k = 0; k < 32; ++k) s += mask[(b << 11) + Eidx[nd * 32 + k]];
            g_vs[nd] = s;
        }
    }
}

// ---------------- embed_edge: persistent, double-buffered staging ----------
#define SM_EE (16384 * 2 + (12288 + 896) * 4)
__global__ void __launch_bounds__(256, 2)
embed_edge_k(const float* __restrict__ E, const float* __restrict__ bb,
             const float* __restrict__ gg, const float* __restrict__ b2) {
    extern __shared__ __half smh[];
    __half* sAh = smh; __half* sWh = smh + 8192;
    float* fx = (float*)(smh + 16384);
    float* stage = fx;
    float* sBias = fx + 12288; float* sG = fx + 12416; float* sB2 = fx + 12544;
    float* sRS = fx + 12672; float* sRQ = fx + 12928;
    uint32_t sAu = s2u(sAh), sWu = s2u(sWh);
    int tid = threadIdx.x, lane = tid & 31, wid = tid >> 5;
    int g = lane >> 2, t = lane & 3;
    int mbase = (wid & 3) * 32, nbase = (wid >> 2) * 64;

    cpa_h<128, 64>(sWu, g_Wt + 16384, tid);   // We
    {
        uint32_t dst = s2u(stage);
        const float* src = E + (size_t)blockIdx.x * 128 * 48;
        #pragma unroll
        for (int i = tid; i < 1536; i += 256) CP16(dst + i * 16, src + i * 4);
    }
    CP_COMMIT();
    if (tid < 128) { sBias[tid] = bb[tid]; sG[tid] = gg[tid]; sB2[tid] = b2[tid]; }

    int cur = 0;
    for (int tile = blockIdx.x; tile < 1024; tile += gridDim.x) {
        int nxt = tile + gridDim.x;
        if (nxt < 1024) {
            uint32_t dst = s2u(stage + (1 - cur) * 6144);
            const float* src = E + (size_t)nxt * 128 * 48;
            #pragma unroll
            for (int i = tid; i < 1536; i += 256) CP16(dst + i * 16, src + i * 4);
            CP_COMMIT(); CP_WAIT1();
        } else {
            CP_WAIT0();
        }
        __syncthreads();
        const float* st = stage + cur * 6144;
        for (int i = tid; i < 1024; i += 256) {
            int r = i >> 3, gc = (i & 7) * 8;
            uint4 u;
            if (gc < 48) {
                const float* xp = st + r * 48 + gc;
                float4 v0 = *(const float4*)xp;
                float4 v1 = *(const float4*)(xp + 4);
                u.x = f2h2(v0.x, v0.y); u.y = f2h2(v0.z, v0.w);
                u.z = f2h2(v1.x, v1.y); u.w = f2h2(v1.z, v1.w);
            } else u = make_uint4(0, 0, 0, 0);
            *(uint4*)((char*)sAh + swzh<64>(r, gc) * 2) = u;
        }
        __syncthreads();

        float acc[2][8][4];
        zacc8(acc);
        cta_gemm_h<4, 64>(sAu, sWu, lane, mbase, nbase, acc);

        float p[4] = {0, 0, 0, 0}, q[4] = {0, 0, 0, 0};
        #pragma unroll
        for (int mt = 0; mt < 2; ++mt)
            #pragma unroll
            for (int nt = 0; nt < 8; ++nt) {
                int c0 = nbase + nt * 8 + t * 2;
                float* d = acc[mt][nt];
                d[0] += sBias[c0]; d[1] += sBias[c0 + 1];
                d[2] += sBias[c0]; d[3] += sBias[c0 + 1];
                p[mt*2]   += d[0] + d[1];  q[mt*2]   += d[0]*d[0] + d[1]*d[1];
                p[mt*2+1] += d[2] + d[3];  q[mt*2+1] += d[2]*d[2] + d[3]*d[3];
            }
        #pragma unroll
        for (int i = 0; i < 4; ++i) {
            p[i] += __shfl_xor_sync(0xffffffffu, p[i], 1);
            p[i] += __shfl_xor_sync(0xffffffffu, p[i], 2);
            q[i] += __shfl_xor_sync(0xffffffffu, q[i], 1);
            q[i] += __shfl_xor_sync(0xffffffffu, q[i], 2);
        }
        int half_ = nbase >> 6;
        if (t == 0) {
            #pragma unroll
            for (int i = 0; i < 4; ++i) {
                int r = mbase + (i >> 1) * 16 + (i & 1) * 8 + g;
                sRS[r * 2 + half_] = p[i];
                sRQ[r * 2 + half_] = q[i];
            }
        }
        __syncthreads();
        #pragma unroll
        for (int mt = 0; mt < 2; ++mt)
            #pragma unroll
            for (int jj = 0; jj < 2; ++jj) {
                int r = mbase + mt * 16 + jj * 8 + g;
                float mu = (sRS[r * 2] + sRS[r * 2 + 1]) * (1.f / 128.f);
                float qq = sRQ[r * 2] + sRQ[r * 2 + 1];
                float var = (qq - 128.f * mu * mu) * (1.f / 127.f);
                float inv = 1.f / (sqrtf(fmaxf(var, 0.f)) + 1e-6f);
                #pragma unroll
                for (int nt = 0; nt < 8; ++nt) {
                    int c0 = nbase + nt * 8 + t * 2;
                    float* d = acc[mt][nt];
                    float v0 = sG[c0]     * (d[jj*2]   - mu) * inv + sB2[c0];
                    float v1 = sG[c0 + 1] * (d[jj*2+1] - mu) * inv + sB2[c0 + 1];
                    *(uint32_t*)(g_her + ((size_t)tile * 128 + r) * 128 + c0) = f2h2(v0, v1);
                }
            }
        __syncthreads();
        cur ^= 1;
    }
}

// ---------------- edge layer: persistent, resident weights, A prefetch ------
#define SM_EDGE (49152 * 2 + 896 * 4)
__global__ void __launch_bounds__(256, 2)
edge_layer_k(const int* __restrict__ Eidx, const float* __restrict__ mask,
             const float* __restrict__ Lb2, int layer) {
    extern __shared__ __half smh[];
    __half* sAh = smh; __half* sB0h = smh + 16384; __half* sB1h = smh + 32768;
    float* fx = (float*)(smh + 49152);
    float* sP1 = fx; float* sVm = fx + 512; float* sBb2 = fx + 640;
    int* sGidx = (int*)(fx + 768);
    uint32_t sAu = s2u(sAh), sB0u = s2u(sB0h), sB1u = s2u(sB1h);
    int tid = threadIdx.x, lane = tid & 31, wid = tid >> 5;
    int wbase = 2 + layer * 6;
    int mbase = (wid & 3) * 32, nbase = (wid >> 2) * 64;
    int g = lane >> 2, t = lane & 3;

    cpa_h<128, 128>(sB0u, g_Wt + (size_t)(wbase + 3) * 16384, tid);  // W1q3
    cpa_h<128, 128>(sB1u, g_Wt + (size_t)(wbase + 4) * 16384, tid);  // Lw2
    if ((int)blockIdx.x < 1024)
        cpa_h<128, 128>(sAu, g_her + (size_t)blockIdx.x * 16384, tid);
    CP_COMMIT();
    if (tid < 128) sBb2[tid] = Lb2[layer * 128 + tid];

    for (int tile = blockIdx.x; tile < 1024; tile += gridDim.x) {
        __syncthreads();
        int base4 = tile * 4;
        if (tid < 128) {
            int nd = base4 + (tid >> 5);
            int idx = Eidx[nd * 32 + (tid & 31)];
            int gi = ((nd >> 11) << 11) + idx;
            sGidx[tid] = gi;
            sVm[tid] = mask[gi];
        }
        // P1 via cp.async, joins outstanding group
        {
            uint32_t dst = s2u(sP1);
            const float* src = g_P1 + (size_t)base4 * 128;
            #pragma unroll
            for (int i = tid; i < 128; i += 256) CP16(dst + i * 16, src + i * 4);
            CP_COMMIT();
        }
        CP_WAIT0(); __syncthreads();

        float acc[2][8][4];
        zacc8(acc);
        cta_gemm_h<8, 128>(sAu, sB0u, lane, mbase, nbase, acc);
        __syncthreads();

        // epilogue1: relu(D + P1 + P23gather[fp16]) -> sAh
        #pragma unroll
        for (int mt = 0; mt < 2; ++mt) {
            int r0 = mbase + mt * 16 + g, r1 = r0 + 8;
            const __half* p23a = g_P23 + (size_t)sGidx[r0] * 128;
            const __half* p23b = g_P23 + (size_t)sGidx[r1] * 128;
            const float* p1a = sP1 + ((r0 >> 5) << 7);
            const float* p1b = sP1 + ((r1 >> 5) << 7);
            #pragma unroll
            for (int nt = 0; nt < 8; ++nt) {
                int c0 = nbase + nt * 8 + t * 2;
                float* d = acc[mt][nt];
                float2 qa = __half22float2(*(const __half2*)(p23a + c0));
                float2 qb = __half22float2(*(const __half2*)(p23b + c0));
                *(uint32_t*)((char*)sAh + swzh<128>(r0, c0) * 2) =
                    f2h2(fmaxf(d[0] + qa.x + p1a[c0], 0.f), fmaxf(d[1] + qa.y + p1a[c0+1], 0.f));
                *(uint32_t*)((char*)sAh + swzh<128>(r1, c0) * 2) =
                    f2h2(fmaxf(d[2] + qb.x + p1b[c0], 0.f), fmaxf(d[3] + qb.y + p1b[c0+1], 0.f));
            }
        }
        __syncthreads();

        zacc8(acc);
        cta_gemm_h<8, 128>(sAu, sB1u, lane, mbase, nbase, acc);
        __syncthreads();                       // all warps done reading sAh

        int nxt = tile + gridDim.x;            // prefetch next A during epilogue2
        if (nxt < 1024) {
            cpa_h<128, 128>(sAu, g_her + (size_t)nxt * 16384, tid);
            CP_COMMIT();
        }

        // epilogue2: weighted segment sum of relu(D + b2)
        float part[8][2];
        #pragma unroll
        for (int nt = 0; nt < 8; ++nt) { part[nt][0] = 0.f; part[nt][1] = 0.f; }
        #pragma unroll
        for (int mt = 0; mt < 2; ++mt) {
            int r0 = mbase + mt * 16 + g, r1 = r0 + 8;
            float v0 = sVm[r0], v1 = sVm[r1];
            #pragma unroll
            for (int nt = 0; nt < 8; ++nt) {
                int c0 = nbase + nt * 8 + t * 2;
                float* d = acc[mt][nt];
                part[nt][0] += fmaxf(d[0] + sBb2[c0],   0.f) * v0
                             + fmaxf(d[2] + sBb2[c0],   0.f) * v1;
                part[nt][1] += fmaxf(d[1] + sBb2[c0+1], 0.f) * v0
                             + fmaxf(d[3] + sBb2[c0+1], 0.f) * v1;
            }
        }
        #pragma unroll
        for (int nt = 0; nt < 8; ++nt)
            #pragma unroll
            for (int j = 0; j < 2; ++j) {
                float v = part[nt][j];
                v += __shfl_xor_sync(0xffffffffu, v, 4);
                v += __shfl_xor_sync(0xffffffffu, v, 8);
                v += __shfl_xor_sync(0xffffffffu, v, 16);
                part[nt][j] = v;
            }
        if (g == 0) {
            int node = base4 + (wid & 3);
            #pragma unroll
            for (int nt = 0; nt < 8; ++nt) {
                int c0 = nbase + nt * 8 + t * 2;
                *(uint32_t*)(g_S2h + (size_t)node * 128 + c0) = f2h2(part[nt][0], part[nt][1]);
            }
        }
    }
}

// ---------------- proj phase (M=64): P1 = h@W0+b1 ; P23[fp16] = h@W1 + hS@W2 -
__device__ __forceinline__ void proj_phase64(uint32_t sA2u, uint32_t sA1u,
                                             uint32_t sW0u, uint32_t sW1u, uint32_t sW2u,
                                             const float* sBias1, int blk,
                                             int lane, int wid) {
    int mbase = (wid & 1) * 32, nbase = (wid >> 1) * 32;
    int g = lane >> 2, t = lane & 3;
    float acc[2][4][4];

    zacc4(acc);
    cta_gemm64<8, 128>(sA2u, sW0u, lane, mbase, nbase, acc);
    #pragma unroll
    for (int mt = 0; mt < 2; ++mt) {
        int r0 = mbase + mt * 16 + g;
        #pragma unroll
        for (int nt = 0; nt < 4; ++nt) {
            int c0 = nbase + nt * 8 + t * 2;
            float* d = acc[mt][nt];
            *(float2*)(g_P1 + ((size_t)blk * 64 + r0) * 128 + c0) =
                make_float2(d[0] + sBias1[c0], d[1] + sBias1[c0 + 1]);
            *(float2*)(g_P1 + ((size_t)blk * 64 + r0 + 8) * 128 + c0) =
                make_float2(d[2] + sBias1[c0], d[3] + sBias1[c0 + 1]);
        }
    }
    zacc4(acc);
    cta_gemm64<8, 128>(sA2u, sW1u, lane, mbase, nbase, acc);
    CP_WAIT0(); __syncthreads();
    cta_gemm64<8, 128>(sA1u, sW2u, lane, mbase, nbase, acc);
    #pragma unroll
    for (int mt = 0; mt < 2; ++mt) {
        int r0 = mbase + mt * 16 + g;
        #pragma unroll
        for (int nt = 0; nt < 4; ++nt) {
            int c0 = nbase + nt * 8 + t * 2;
            float* d = acc[mt][nt];
            *(uint32_t*)(g_P23 + ((size_t)blk * 64 + r0) * 128 + c0) = f2h2(d[0], d[1]);
            *(uint32_t*)(g_P23 + ((size_t)blk * 64 + r0 + 8) * 128 + c0) = f2h2(d[2], d[3]);
        }
    }
}

#define SM_NP ((8192 * 2 + 3 * 16384) * 2 + 1152 * 4)

// ---------------- embed_node + proj(layer 0), M=64, grid 64 -----------------
__global__ void __launch_bounds__(256)
embed_node_proj_k(const float* __restrict__ V, const float* __restrict__ bb,
                  const float* __restrict__ gg, const float* __restrict__ b2,
                  const float* __restrict__ Lb1) {
    extern __shared__ __half smh[];
    __half* sA1 = smh;            __half* sA2 = smh + 8192;
    __half* sW0 = smh + 16384;    __half* sW1 = smh + 32768;  __half* sW2 = smh + 49152;
    float* fx = (float*)(smh + 65536);
    float* sBias = fx; float* sG = fx + 128; float* sB2 = fx + 256;
    float* sBias1 = fx + 384;
    float* sRS = fx + 512; float* sRQ = fx + 768;
    uint32_t sA1u = s2u(sA1), sA2u = s2u(sA2);
    uint32_t sW0u = s2u(sW0), sW1u = s2u(sW1), sW2u = s2u(sW2);
    int tid = threadIdx.x, lane = tid & 31, wid = tid >> 5, blk = blockIdx.x;
    int g = lane >> 2, t = lane & 3;
    int mbase = (wid & 1) * 32, nbase = (wid >> 1) * 32;
    int ng = wid >> 1;

    cpa_h<128, 64>(sW2u, g_Wt, tid);
    cpa_h<128, 128>(sW0u, g_Wt + (size_t)2 * 16384, tid);
    cpa_h<128, 128>(sW1u, g_Wt + (size_t)3 * 16384, tid);
    CP_COMMIT();
    for (int i = tid; i < 512; i += 256) {
        int r = i >> 3, gc = (i & 7) * 8;
        const float* xp = V + ((size_t)blk * 64 + r) * 64 + gc;
        float4 v0 = *(const float4*)xp;
        float4 v1 = *(const float4*)(xp + 4);
        uint4 u;
        u.x = f2h2(v0.x, v0.y); u.y = f2h2(v0.z, v0.w);
        u.z = f2h2(v1.x, v1.y); u.w = f2h2(v1.z, v1.w);
        *(uint4*)((char*)sA1 + swzh<64>(r, gc) * 2) = u;
    }
    if (tid < 128) {
        sBias[tid] = bb[tid]; sG[tid] = gg[tid]; sB2[tid] = b2[tid];
        sBias1[tid] = Lb1[tid];
    }
    CP_WAIT0(); __syncthreads();

    float acc[2][4][4];
    zacc4(acc);
    cta_gemm64<4, 64>(sA1u, sW2u, lane, mbase, nbase, acc);
    __syncthreads();
    cpa_h<64, 128>(sA1u, g_hSr + (size_t)blk * 8192, tid);
    cpa_h<128, 128>(sW2u, g_Wt + (size_t)4 * 16384, tid);
    CP_COMMIT();

    float p[4] = {0,0,0,0}, q[4] = {0,0,0,0};
    #pragma unroll
    for (int mt = 0; mt < 2; ++mt)
        #pragma unroll
        for (int nt = 0; nt < 4; ++nt) {
            int c0 = nbase + nt * 8 + t * 2;
            float* d = acc[mt][nt];
            d[0] += sBias[c0]; d[1] += sBias[c0 + 1];
            d[2] += sBias[c0]; d[3] += sBias[c0 + 1];
            p[mt*2]   += d[0] + d[1];  q[mt*2]   += d[0]*d[0] + d[1]*d[1];
            p[mt*2+1] += d[2] + d[3];  q[mt*2+1] += d[2]*d[2] + d[3]*d[3];
        }
    #pragma unroll
    for (int i = 0; i < 4; ++i) {
        p[i] += __shfl_xor_sync(0xffffffffu, p[i], 1);
        p[i] += __shfl_xor_sync(0xffffffffu, p[i], 2);
        q[i] += __shfl_xor_sync(0xffffffffu, q[i], 1);
        q[i] += __shfl_xor_sync(0xffffffffu, q[i], 2);
    }
    if (t == 0) {
        #pragma unroll
        for (int i = 0; i < 4; ++i) {
            int r = mbase + (i >> 1) * 16 + (i & 1) * 8 + g;
            sRS[r * 4 + ng] = p[i];
            sRQ[r * 4 + ng] = q[i];
        }
    }
    __syncthreads();
    #pragma unroll
    for (int mt = 0; mt < 2; ++mt)
        #pragma unroll
        for (int jj = 0; jj < 2; ++jj) {
            int r = mbase + mt * 16 + jj * 8 + g;
            float mu = (sRS[r*4] + sRS[r*4+1] + sRS[r*4+2] + sRS[r*4+3]) * (1.f / 128.f);
            float qq = sRQ[r*4] + sRQ[r*4+1] + sRQ[r*4+2] + sRQ[r*4+3];
            float var = (qq - 128.f * mu * mu) * (1.f / 127.f);
            float inv = 1.f / (sqrtf(fmaxf(var, 0.f)) + 1e-6f);
            #pragma unroll
            for (int nt = 0; nt < 4; ++nt) {
                int c0 = nbase + nt * 8 + t * 2;
                float* d = acc[mt][nt];
                float v0 = sG[c0]     * (d[jj*2]   - mu) * inv + sB2[c0];
                float v1 = sG[c0 + 1] * (d[jj*2+1] - mu) * inv + sB2[c0 + 1];
                *(float2*)(g_h + ((size_t)blk * 64 + r) * 128 + c0) = make_float2(v0, v1);
                *(uint32_t*)((char*)sA2 + swzh<128>(r, c0) * 2) = f2h2(v0, v1);
            }
        }
    __syncthreads();
    proj_phase64(sA2u, sA1u, sW0u, sW1u, sW2u, sBias1, blk, lane, wid);
}

// ---------------- node_fused: fin(layer) + proj(layer+1), M=64 --------------
__global__ void __launch_bounds__(256)
node_fused_k(const float* __restrict__ mask, const float* __restrict__ Lb3,
             const float* __restrict__ Lng, const float* __restrict__ Lnb,
             const float* __restrict__ Lb1, int layer, int last,
             float* __restrict__ outp) {
    extern __shared__ __half smh[];
    __half* sA1 = smh;            __half* sA2 = smh + 8192;
    __half* sW0 = smh + 16384;    __half* sW1 = smh + 32768;  __half* sW2 = smh + 49152;
    float* fx = (float*)(smh + 65536);
    float* sB3 = fx; float* sLg = fx + 128; float* sLb = fx + 256;
    float* sBias1 = fx + 384;
    float* sRS = fx + 512; float* sRQ = fx + 768;
    float* sVs = fx + 1024; float* sMk = fx + 1088;
    uint32_t sA1u = s2u(sA1), sA2u = s2u(sA2);
    uint32_t sW0u = s2u(sW0), sW1u = s2u(sW1), sW2u = s2u(sW2);
    int tid = threadIdx.x, lane = tid & 31, wid = tid >> 5, blk = blockIdx.x;
    int wbase = 2 + layer * 6, wnext = 2 + (layer + 1) * 6;
    int g = lane >> 2, t = lane & 3;
    int mbase = (wid & 1) * 32, nbase = (wid >> 1) * 32;
    int ng = wid >> 1;

    cpa_h<64, 128>(sA1u, g_S2h + (size_t)blk * 8192, tid);
    cpa_h<128, 128>(sW2u, g_Wt + (size_t)(wbase + 5) * 16384, tid);
    if (!last) {
        cpa_h<128, 128>(sW0u, g_Wt + (size_t)(wnext + 0) * 16384, tid);
        cpa_h<128, 128>(sW1u, g_Wt + (size_t)(wnext + 1) * 16384, tid);
    }
    CP_COMMIT();
    if (tid < 128) {
        sB3[tid] = Lb3[layer * 128 + tid];
        sLg[tid] = Lng[layer * 128 + tid];
        sLb[tid] = Lnb[layer * 128 + tid];
        if (!last) sBias1[tid] = Lb1[(layer + 1) * 128 + tid];
    }
    if (tid < 64) {
        sVs[tid] = g_vs[blk * 64 + tid];
        sMk[tid] = mask[blk * 64 + tid];
    }
    CP_WAIT0(); __syncthreads();

    float acc[2][4][4];
    zacc4(acc);
    cta_gemm64<8, 128>(sA1u, sW2u, lane, mbase, nbase, acc);
    __syncthreads();
    if (!last) {
        cpa_h<64, 128>(sA1u, g_hSr + (size_t)blk * 8192, tid);
        cpa_h<128, 128>(sW2u, g_Wt + (size_t)(wnext + 2) * 16384, tid);
        CP_COMMIT();
    }

    const float i30 = 1.f / 30.f;
    float p[4] = {0,0,0,0}, q[4] = {0,0,0,0};
    #pragma unroll
    for (int mt = 0; mt < 2; ++mt) {
        int r0 = mbase + mt * 16 + g, r1 = r0 + 8;
        float vs0 = sVs[r0] * i30, vs1 = sVs[r1] * i30;
        #pragma unroll
        for (int nt = 0; nt < 4; ++nt) {
            int c0 = nbase + nt * 8 + t * 2;
            float* d = acc[mt][nt];
            float2 h0 = *(const float2*)(g_h + ((size_t)(blk * 64 + r0)) * 128 + c0);
            float2 h1 = *(const float2*)(g_h + ((size_t)(blk * 64 + r1)) * 128 + c0);
            d[0] = d[0] * i30 + vs0 * sB3[c0]     + h0.x;
            d[1] = d[1] * i30 + vs0 * sB3[c0 + 1] + h0.y;
            d[2] = d[2] * i30 + vs1 * sB3[c0]     + h1.x;
            d[3] = d[3] * i30 + vs1 * sB3[c0 + 1] + h1.y;
            p[mt*2]   += d[0] + d[1];  q[mt*2]   += d[0]*d[0] + d[1]*d[1];
            p[mt*2+1] += d[2] + d[3];  q[mt*2+1] += d[2]*d[2] + d[3]*d[3];
        }
    }
    #pragma unroll
    for (int i = 0; i < 4; ++i) {
        p[i] += __shfl_xor_sync(0xffffffffu, p[i], 1);
        p[i] += __shfl_xor_sync(0xffffffffu, p[i], 2);
        q[i] += __shfl_xor_sync(0xffffffffu, q[i], 1);
        q[i] += __shfl_xor_sync(0xffffffffu, q[i], 2);
    }
    if (t == 0) {
        #pragma unroll
        for (int i = 0; i < 4; ++i) {
            int r = mbase + (i >> 1) * 16 + (i & 1) * 8 + g;
            sRS[r * 4 + ng] = p[i];
            sRQ[r * 4 + ng] = q[i];
        }
    }
    __syncthreads();
    #pragma unroll
    for (int mt = 0; mt < 2; ++mt)
        #pragma unroll
        for (int jj = 0; jj < 2; ++jj) {
            int r = mbase + mt * 16 + jj * 8 + g;
            float mu = (sRS[r*4] + sRS[r*4+1] + sRS[r*4+2] + sRS[r*4+3]) * (1.f / 128.f);
            float qq = sRQ[r*4] + sRQ[r*4+1] + sRQ[r*4+2] + sRQ[r*4+3];
            float var = (qq - 128.f * mu * mu) * (1.f / 127.f);
            float inv = 1.f / (sqrtf(fmaxf(var, 0.f)) + 1e-6f);
            float mk = sMk[r];
            #pragma unroll
            for (int nt = 0; nt < 4; ++nt) {
                int c0 = nbase + nt * 8 + t * 2;
                float* d = acc[mt][nt];
                float v0 = (sLg[c0]     * (d[jj*2]   - mu) * inv + sLb[c0])     * mk;
                float v1 = (sLg[c0 + 1] * (d[jj*2+1] - mu) * inv + sLb[c0 + 1]) * mk;
                size_t off = ((size_t)blk * 64 + r) * 128 + c0;
                if (last) {
                    *(float2*)(outp + off) = make_float2(v0, v1);
                } else {
                    *(float2*)(g_h + off) = make_float2(v0, v1);
                    *(uint32_t*)((char*)sA2 + swzh<128>(r, c0) * 2) = f2h2(v0, v1);
                }
            }
        }
    if (last) return;
    __syncthreads();
    proj_phase64(sA2u, sA1u, sW0u, sW1u, sW2u, sBias1, blk, lane, wid);
}

// ---------------- launch ----------------
extern "C" void kernel_launch(void* const* d_in, const int* in_sizes, int n_in,
                              void* d_out, int out_size) {
    const float* V     = (const float*)d_in[0];
    const float* E     = (const float*)d_in[1];
    const float* hS    = (const float*)d_in[2];
    const int*   E_idx = (const int*)  d_in[3];
    const float* mask  = (const float*)d_in[4];
    const float* Wv_w  = (const float*)d_in[5];
    const float* Wv_b  = (const float*)d_in[6];
    const float* Wv_g  = (const float*)d_in[7];
    const float* Wv_b2 = (const float*)d_in[8];
    const float* We_w  = (const float*)d_in[9];
    const float* We_b  = (const float*)d_in[10];
    const float* We_g  = (const float*)d_in[11];
    const float* We_b2 = (const float*)d_in[12];
    const float* Lw1   = (const float*)d_in[13];
    const float* Lb1   = (const float*)d_in[14];
    const float* Lw2   = (const float*)d_in[15];
    const float* Lb2   = (const float*)d_in[16];
    const float* Lw3   = (const float*)d_in[17];
    const float* Lb3   = (const float*)d_in[18];
    const float* Ln_g  = (const float*)d_in[19];
    const float* Ln_b  = (const float*)d_in[20];
    float* out = (float*)d_out;

    cudaFuncSetAttribute(embed_edge_k,      cudaFuncAttributeMaxDynamicSharedMemorySize, SM_EE);
    cudaFuncSetAttribute(edge_layer_k,      cudaFuncAttributeMaxDynamicSharedMemorySize, SM_EDGE);
    cudaFuncSetAttribute(embed_node_proj_k, cudaFuncAttributeMaxDynamicSharedMemorySize, SM_NP);
    cudaFuncSetAttribute(node_fused_k,      cudaFuncAttributeMaxDynamicSharedMemorySize, SM_NP);

    pack_all<<<68, 256>>>(Wv_w, We_w, Lw1, Lw2, Lw3, hS, E_idx, mask);
    embed_node_proj_k<<<64, 256, SM_NP>>>(V, Wv_b, Wv_g, Wv_b2, Lb1);
    embed_edge_k<<<304, 256, SM_EE>>>(E, We_b, We_g, We_b2);

    for (int layer = 0; layer < 3; ++layer) {
        edge_layer_k<<<304, 256, SM_EDGE>>>(E_idx, mask, Lb2, layer);
        node_fused_k<<<64, 256, SM_NP>>>(mask, Lb3, Ln_g, Ln_b, Lb1,
                                         layer, layer == 2 ? 1 : 0, out);
    }
}